// round 7
// baseline (speedup 1.0000x reference)
#include <cuda_runtime.h>
#include <cstdint>

// ---------------------------------------------------------------------------
// DGCNN: 2x EdgeConv (dynamic kNN) + final MLP, training-mode BatchNorm.
// R7 = R6 (occupancy fix: 8x8 microtile, 256thr, launch_bounds(256,2),
// register-prefetch) with the gemm_nodes STATS shared-memory OOB fixed:
// sumsq now goes to Bs only when it fits (BN=128), else upper half of As.
// ---------------------------------------------------------------------------

typedef unsigned long long ull;

namespace cfg {
constexpr int BB   = 8;
constexpr int NN_  = 1024;
constexpr int KNN  = 20;
constexpr int NROW  = BB * NN_;        // 8192
constexpr int NEDGE = NROW * KNN;      // 163840

constexpr size_t OFF_D    = 0;
constexpr size_t SZ_D     = (size_t)BB * NN_ * NN_;
constexpr size_t OFF_PQ   = OFF_D + SZ_D;
constexpr size_t SZ_PQ    = (size_t)NROW * 128;
constexpr size_t OFF_PQ2  = OFF_PQ + SZ_PQ;
constexpr size_t SZ_PQ2   = (size_t)NROW * 256;
constexpr size_t OFF_H1   = OFF_PQ2 + SZ_PQ2;
constexpr size_t SZ_H64   = (size_t)NEDGE * 64;
constexpr size_t OFF_H2   = OFF_H1 + SZ_H64;
constexpr size_t OFF_HCAT = OFF_H2 + SZ_H64;
constexpr size_t SZ_HCAT  = (size_t)NROW * 192;
constexpr size_t OFF_X1   = OFF_HCAT + SZ_HCAT;
constexpr size_t SZ_X1    = (size_t)NROW * 64;
constexpr size_t OFF_Y0   = OFF_X1 + SZ_X1;
constexpr size_t SZ_Y0    = (size_t)NROW * 128;
constexpr size_t OFF_SQ   = OFF_Y0 + SZ_Y0;
constexpr size_t SZ_SQ    = (size_t)NROW;
constexpr size_t OFF_WCAT = OFF_SQ + SZ_SQ;
constexpr size_t SZ_WCAT  = 256 * 128;
constexpr size_t OFF_WCAT2= OFF_WCAT + SZ_WCAT;
constexpr size_t SZ_WCAT2 = 64 * 256;
constexpr size_t OFF_WF   = OFF_WCAT2 + SZ_WCAT2;
constexpr size_t SZ_WF    = 64 * 64;
constexpr size_t OFF_BF   = OFF_WF + SZ_WF;
constexpr size_t SZ_BF    = 128;
constexpr size_t SCRATCH_TOTAL = OFF_BF + SZ_BF;
}  // namespace cfg
using namespace cfg;

__device__ float  g_scratch[SCRATCH_TOTAL];
__device__ int    g_knn_idx[NEDGE];
__device__ double g_sum[128];
__device__ double g_sumsq[128];
__device__ float  g_sc[128];
__device__ float  g_cc[128];

// ---------------------------------------------------------------------------
__device__ __forceinline__ ull pack2(float x, float y) {
    ull r; asm("mov.b64 %0, {%1, %2};" : "=l"(r) : "f"(x), "f"(y)); return r;
}
__device__ __forceinline__ void fma2(ull& d, ull a, ull b) {
    asm("fma.rn.f32x2 %0, %1, %2, %0;" : "+l"(d) : "l"(a), "l"(b));
}
__device__ __forceinline__ float2 unpack2(ull v) {
    float2 f; asm("mov.b64 {%0, %1}, %2;" : "=f"(f.x), "=f"(f.y) : "l"(v)); return f;
}

// ---------------------------------------------------------------------------
// Combined weights [A-B | B]  (dependency-free; launched first so the ncu
// capture slot lands on dist_kernel)
// ---------------------------------------------------------------------------
__global__ void build_wcat1(const float* __restrict__ W0, float* __restrict__ Wcat) {
    int e = blockIdx.x * 256 + threadIdx.x;    // 256*128
    int kk = e >> 7, n = e & 127;
    float v;
    if (n < 64) v = W0[kk * 64 + n] - W0[(kk + 256) * 64 + n];
    else        v = W0[(kk + 256) * 64 + (n - 64)];
    Wcat[e] = v;
}
__global__ void build_wcat2(const float* __restrict__ W0, float* __restrict__ Wcat) {
    int e = blockIdx.x * 256 + threadIdx.x;    // 64*256
    int kk = e >> 8, n = e & 255;
    float v;
    if (n < 128) v = W0[kk * 128 + n] - W0[(kk + 64) * 128 + n];
    else         v = W0[(kk + 64) * 128 + (n - 128)];
    Wcat[e] = v;
}

// ---------------------------------------------------------------------------
template <int C>
__global__ void rowsq_kernel(const float* __restrict__ X, float* __restrict__ sq) {
    int row = blockIdx.x;
    const float* x = X + (size_t)row * C;
    float a = 0.f;
    #pragma unroll
    for (int c = threadIdx.x; c < C; c += 32) { float v = x[c]; a = fmaf(v, v, a); }
    #pragma unroll
    for (int o = 16; o; o >>= 1) a += __shfl_xor_sync(0xffffffffu, a, o);
    if (threadIdx.x == 0) sq[row] = a;
}

// ---------------------------------------------------------------------------
// Distance matrix: 256 threads, BM=BN=128, BK=16, microtile 8(4 pairs) x 8(j)
// Register-prefetch of GMEM tiles overlaps LDG with previous tile compute.
// ---------------------------------------------------------------------------
template <int C>
__global__ void __launch_bounds__(256, 2)
dist_kernel(const float* __restrict__ X, const float* __restrict__ sq,
            float* __restrict__ D) {
    __shared__ float As[16][128];
    __shared__ float Bs[16][128];
    int b  = blockIdx.z;
    const float* Xb  = X  + (size_t)b * NN_ * C;
    const float* sqb = sq + (size_t)b * NN_;
    float* Db = D + (size_t)b * NN_ * NN_;
    int i0 = blockIdx.y * 128, j0 = blockIdx.x * 128;
    int t  = threadIdx.x;
    int tx = t & 15, ty = t >> 4;

    int lr  = t >> 1;
    int lc0 = (t & 1) * 8;

    ull acc[4][8];
    #pragma unroll
    for (int p = 0; p < 4; p++)
        #pragma unroll
        for (int j = 0; j < 8; j++) acc[p][j] = 0ull;

    for (int k0 = 0; k0 < C; k0 += 16) {
        float4 pa0 = *reinterpret_cast<const float4*>(&Xb[(size_t)(i0 + lr) * C + k0 + lc0]);
        float4 pa1 = *reinterpret_cast<const float4*>(&Xb[(size_t)(i0 + lr) * C + k0 + lc0 + 4]);
        float4 pb0 = *reinterpret_cast<const float4*>(&Xb[(size_t)(j0 + lr) * C + k0 + lc0]);
        float4 pb1 = *reinterpret_cast<const float4*>(&Xb[(size_t)(j0 + lr) * C + k0 + lc0 + 4]);
        __syncthreads();
        As[lc0 + 0][lr] = pa0.x; As[lc0 + 1][lr] = pa0.y;
        As[lc0 + 2][lr] = pa0.z; As[lc0 + 3][lr] = pa0.w;
        As[lc0 + 4][lr] = pa1.x; As[lc0 + 5][lr] = pa1.y;
        As[lc0 + 6][lr] = pa1.z; As[lc0 + 7][lr] = pa1.w;
        Bs[lc0 + 0][lr] = pb0.x; Bs[lc0 + 1][lr] = pb0.y;
        Bs[lc0 + 2][lr] = pb0.z; Bs[lc0 + 3][lr] = pb0.w;
        Bs[lc0 + 4][lr] = pb1.x; Bs[lc0 + 5][lr] = pb1.y;
        Bs[lc0 + 6][lr] = pb1.z; Bs[lc0 + 7][lr] = pb1.w;
        __syncthreads();
        #pragma unroll
        for (int kk = 0; kk < 16; kk++) {
            const ulonglong2* ap = reinterpret_cast<const ulonglong2*>(&As[kk][ty * 8]);
            ulonglong2 aa = ap[0], ab = ap[1];
            ull ra[4] = {aa.x, aa.y, ab.x, ab.y};
            float4 b0 = *reinterpret_cast<const float4*>(&Bs[kk][tx * 8]);
            float4 b1 = *reinterpret_cast<const float4*>(&Bs[kk][tx * 8 + 4]);
            float fb[8] = {b0.x, b0.y, b0.z, b0.w, b1.x, b1.y, b1.z, b1.w};
            #pragma unroll
            for (int j = 0; j < 8; j++) {
                ull bj = pack2(fb[j], fb[j]);
                #pragma unroll
                for (int p = 0; p < 4; p++) fma2(acc[p][j], ra[p], bj);
            }
        }
    }
    float sj[8];
    #pragma unroll
    for (int j = 0; j < 8; j++) sj[j] = sqb[j0 + tx * 8 + j];
    #pragma unroll
    for (int p = 0; p < 4; p++) {
        int gi = i0 + ty * 8 + 2 * p;
        float si0 = sqb[gi], si1 = sqb[gi + 1];
        float o0[8], o1[8];
        #pragma unroll
        for (int j = 0; j < 8; j++) {
            float2 u = unpack2(acc[p][j]);
            o0[j] = si0 + sj[j] - 2.f * u.x;
            o1[j] = si1 + sj[j] - 2.f * u.y;
        }
        float4* d0 = reinterpret_cast<float4*>(&Db[(size_t)gi * NN_ + j0 + tx * 8]);
        d0[0] = make_float4(o0[0], o0[1], o0[2], o0[3]);
        d0[1] = make_float4(o0[4], o0[5], o0[6], o0[7]);
        float4* d1 = reinterpret_cast<float4*>(&Db[(size_t)(gi + 1) * NN_ + j0 + tx * 8]);
        d1[0] = make_float4(o1[0], o1[1], o1[2], o1[3]);
        d1[1] = make_float4(o1[4], o1[5], o1[6], o1[7]);
    }
}

// ---------------------------------------------------------------------------
// Top-20 smallest per row; one warp per row
// ---------------------------------------------------------------------------
__global__ void topk_kernel(const float* __restrict__ D, int* __restrict__ idx) {
    int row  = blockIdx.x * 8 + (threadIdx.x >> 5);
    int lane = threadIdx.x & 31;
    const float* d = D + (size_t)row * NN_;
    float v[32];
    #pragma unroll
    for (int q = 0; q < 32; q++) v[q] = d[q * 32 + lane];

    for (int s = 0; s < KNN; s++) {
        float m = v[0]; int mq = 0;
        #pragma unroll
        for (int q = 1; q < 32; q++) { if (v[q] < m) { m = v[q]; mq = q; } }
        float bm = m; int bidx = mq * 32 + lane;
        #pragma unroll
        for (int o = 16; o; o >>= 1) {
            float om = __shfl_xor_sync(0xffffffffu, bm, o);
            int   oi = __shfl_xor_sync(0xffffffffu, bidx, o);
            if (om < bm || (om == bm && oi < bidx)) { bm = om; bidx = oi; }
        }
        if (lane == 0) idx[row * KNN + s] = bidx;
        int bl = bidx & 31, bq = bidx >> 5;
        if (lane == bl) {
            #pragma unroll
            for (int q = 0; q < 32; q++) if (q == bq) v[q] = 3.4e38f;
        }
    }
}

// ---------------------------------------------------------------------------
// GEMM: C = A[M,K] @ B[K,N] (+bias,relu)(+stats). 256 threads, BK=16.
// BN=128 -> BM=128; BN=64 -> BM=256. Microtile 8(4 pairs) x 8(j).
// ---------------------------------------------------------------------------
template <int BM, int BN, bool BIAS_RELU, bool STATS>
__global__ void __launch_bounds__(256, 2)
gemm_nodes(const float* __restrict__ A, const float* __restrict__ Bm,
           const float* __restrict__ bias, float* __restrict__ Cmat,
           int M, int N, int K) {
    constexpr int BK  = 16;
    constexpr int TX  = BN / 8;
    constexpr int TYG = 256 / TX;
    static_assert(TYG * 8 == BM, "layout");
    static_assert(TYG * BN == 2048, "stats layout");
    constexpr int N4A = BM / 64;
    constexpr int N4B = BN / 64;
    __shared__ float As[BK * BM];
    __shared__ float Bs[BK * BN];
    int block_m = blockIdx.y * BM, block_n = blockIdx.x * BN;
    int t  = threadIdx.x;
    int tx = t % TX, ty = t / TX;

    ull acc[4][8];
    #pragma unroll
    for (int p = 0; p < 4; p++)
        #pragma unroll
        for (int j = 0; j < 8; j++) acc[p][j] = 0ull;

    for (int k0 = 0; k0 < K; k0 += BK) {
        float4 pa[N4A], pb[N4B];
        #pragma unroll
        for (int i = 0; i < N4A; i++) {
            int f = t * N4A + i; int r = f >> 2, c4 = f & 3;
            pa[i] = *reinterpret_cast<const float4*>(&A[(size_t)(block_m + r) * K + k0 + c4 * 4]);
        }
        #pragma unroll
        for (int i = 0; i < N4B; i++) {
            int f = t * N4B + i; int kk = f / (BN / 4), c4 = f % (BN / 4);
            pb[i] = *reinterpret_cast<const float4*>(&Bm[(size_t)(k0 + kk) * N + block_n + c4 * 4]);
        }
        __syncthreads();
        #pragma unroll
        for (int i = 0; i < N4A; i++) {
            int f = t * N4A + i; int r = f >> 2, c = (f & 3) * 4;
            As[(c + 0) * BM + r] = pa[i].x; As[(c + 1) * BM + r] = pa[i].y;
            As[(c + 2) * BM + r] = pa[i].z; As[(c + 3) * BM + r] = pa[i].w;
        }
        #pragma unroll
        for (int i = 0; i < N4B; i++) {
            int f = t * N4B + i; int kk = f / (BN / 4), c4 = f % (BN / 4);
            *reinterpret_cast<float4*>(&Bs[kk * BN + c4 * 4]) = pb[i];
        }
        __syncthreads();
        #pragma unroll
        for (int kk = 0; kk < BK; kk++) {
            const ulonglong2* ap = reinterpret_cast<const ulonglong2*>(&As[kk * BM + ty * 8]);
            ulonglong2 aa = ap[0], ab = ap[1];
            ull ra[4] = {aa.x, aa.y, ab.x, ab.y};
            float4 b0 = *reinterpret_cast<const float4*>(&Bs[kk * BN + tx * 8]);
            float4 b1 = *reinterpret_cast<const float4*>(&Bs[kk * BN + tx * 8 + 4]);
            float fb[8] = {b0.x, b0.y, b0.z, b0.w, b1.x, b1.y, b1.z, b1.w};
            #pragma unroll
            for (int j = 0; j < 8; j++) {
                ull bj = pack2(fb[j], fb[j]);
                #pragma unroll
                for (int p = 0; p < 4; p++) fma2(acc[p][j], ra[p], bj);
            }
        }
    }

    float bb[8];
    if (BIAS_RELU) {
        #pragma unroll
        for (int j = 0; j < 8; j++) bb[j] = bias[block_n + tx * 8 + j];
    }
    float ps[8], ps2[8];
    #pragma unroll
    for (int j = 0; j < 8; j++) { ps[j] = 0.f; ps2[j] = 0.f; }

    #pragma unroll
    for (int p = 0; p < 4; p++) {
        float v0[8], v1[8];
        #pragma unroll
        for (int j = 0; j < 8; j++) {
            float2 u = unpack2(acc[p][j]);
            v0[j] = u.x; v1[j] = u.y;
            if (BIAS_RELU) { v0[j] = fmaxf(v0[j] + bb[j], 0.f); v1[j] = fmaxf(v1[j] + bb[j], 0.f); }
            if (STATS) { ps[j] += v0[j] + v1[j];
                         ps2[j] = fmaf(v0[j], v0[j], ps2[j]);
                         ps2[j] = fmaf(v1[j], v1[j], ps2[j]); }
        }
        int r = block_m + ty * 8 + 2 * p;
        float4* c0 = reinterpret_cast<float4*>(&Cmat[(size_t)r * N + block_n + tx * 8]);
        c0[0] = make_float4(v0[0], v0[1], v0[2], v0[3]);
        c0[1] = make_float4(v0[4], v0[5], v0[6], v0[7]);
        float4* c1 = reinterpret_cast<float4*>(&Cmat[(size_t)(r + 1) * N + block_n + tx * 8]);
        c1[0] = make_float4(v1[0], v1[1], v1[2], v1[3]);
        c1[1] = make_float4(v1[4], v1[5], v1[6], v1[7]);
    }

    if (STATS) {
        // sums at As[0:2048). sumsq: BN==128 -> Bs (2048 floats exactly);
        // BN==64 (BM=256, As=4096) -> As[2048:4096). No OOB in either case.
        float* SUMS = As;
        float* SQS  = (BN == 128) ? Bs : (As + 2048);
        __syncthreads();
        #pragma unroll
        for (int j = 0; j < 8; j++) {
            SUMS[ty * BN + tx * 8 + j] = ps[j];
            SQS[ty * BN + tx * 8 + j]  = ps2[j];
        }
        __syncthreads();
        if (t < BN) {
            float s = 0.f, s2 = 0.f;
            #pragma unroll
            for (int g = 0; g < TYG; g++) { s += SUMS[g * BN + t]; s2 += SQS[g * BN + t]; }
            atomicAdd(&g_sum[t],   (double)s);
            atomicAdd(&g_sumsq[t], (double)s2);
        }
    }
}

// ---------------------------------------------------------------------------
// Layer-1 edge GEMM: A recomputed on the fly A[e,c]=relu(P[i,c]+Q[j,c]+b[c]).
// BM=256 edge rows, BN=K=64, 256 threads, fused stats, out H1.
// ---------------------------------------------------------------------------
__global__ void __launch_bounds__(256, 2)
gemm_edge1(const float* __restrict__ PQ, const int* __restrict__ IDXp,
           const float* __restrict__ abias, const float* __restrict__ W,
           const float* __restrict__ obias, float* __restrict__ H) {
    __shared__ float As[16 * 256];
    __shared__ float Bs[16 * 64];
    __shared__ int   s_qo[256];
    __shared__ float s_ab[64];
    int t = threadIdx.x;
    int block_m = blockIdx.x * 256;
    {
        int e = block_m + t;
        int bi = e / KNN;
        s_qo[t] = ((bi >> 10) << 10) + IDXp[e];
    }
    if (t < 64) s_ab[t] = abias[t];
    __syncthreads();

    int tx = t & 7, ty = t >> 3;
    int my_bi = (block_m + t) / KNN;
    int my_qo = s_qo[t];
    ull acc[4][8];
    #pragma unroll
    for (int p = 0; p < 4; p++)
        #pragma unroll
        for (int j = 0; j < 8; j++) acc[p][j] = 0ull;

    for (int k0 = 0; k0 < 64; k0 += 16) {
        {
            const float* Pp = PQ + (size_t)my_bi * 128 + k0;
            const float* Qp = PQ + (size_t)my_qo * 128 + 64 + k0;
            float4 pv[4], qv[4];
            #pragma unroll
            for (int q = 0; q < 4; q++) {
                pv[q] = *reinterpret_cast<const float4*>(Pp + q * 4);
                qv[q] = *reinterpret_cast<const float4*>(Qp + q * 4);
            }
            int bkk = t >> 4, bcc = (t & 15) * 4;
            float4 wv = *reinterpret_cast<const float4*>(&W[(size_t)(k0 + bkk) * 64 + bcc]);
            __syncthreads();
            #pragma unroll
            for (int q = 0; q < 4; q++) {
                As[(q * 4 + 0) * 256 + t] = fmaxf(pv[q].x + qv[q].x + s_ab[k0 + q * 4 + 0], 0.f);
                As[(q * 4 + 1) * 256 + t] = fmaxf(pv[q].y + qv[q].y + s_ab[k0 + q * 4 + 1], 0.f);
                As[(q * 4 + 2) * 256 + t] = fmaxf(pv[q].z + qv[q].z + s_ab[k0 + q * 4 + 2], 0.f);
                As[(q * 4 + 3) * 256 + t] = fmaxf(pv[q].w + qv[q].w + s_ab[k0 + q * 4 + 3], 0.f);
            }
            *reinterpret_cast<float4*>(&Bs[bkk * 64 + bcc]) = wv;
        }
        __syncthreads();
        #pragma unroll
        for (int kk = 0; kk < 16; kk++) {
            const ulonglong2* ap = reinterpret_cast<const ulonglong2*>(&As[kk * 256 + ty * 8]);
            ulonglong2 aa = ap[0], ab = ap[1];
            ull ra[4] = {aa.x, aa.y, ab.x, ab.y};
            float4 b0 = *reinterpret_cast<const float4*>(&Bs[kk * 64 + tx * 8]);
            float4 b1 = *reinterpret_cast<const float4*>(&Bs[kk * 64 + tx * 8 + 4]);
            float fb[8] = {b0.x, b0.y, b0.z, b0.w, b1.x, b1.y, b1.z, b1.w};
            #pragma unroll
            for (int j = 0; j < 8; j++) {
                ull bj = pack2(fb[j], fb[j]);
                #pragma unroll
                for (int p = 0; p < 4; p++) fma2(acc[p][j], ra[p], bj);
            }
        }
    }
    float ob[8];
    #pragma unroll
    for (int j = 0; j < 8; j++) ob[j] = obias[tx * 8 + j];
    float ps[8] = {0,0,0,0,0,0,0,0}, ps2[8] = {0,0,0,0,0,0,0,0};
    #pragma unroll
    for (int p = 0; p < 4; p++) {
        float v0[8], v1[8];
        #pragma unroll
        for (int j = 0; j < 8; j++) {
            float2 u = unpack2(acc[p][j]);
            v0[j] = fmaxf(u.x + ob[j], 0.f);
            v1[j] = fmaxf(u.y + ob[j], 0.f);
            ps[j] += v0[j] + v1[j];
            ps2[j] = fmaf(v0[j], v0[j], ps2[j]);
            ps2[j] = fmaf(v1[j], v1[j], ps2[j]);
        }
        int r = block_m + ty * 8 + 2 * p;
        float4* h0 = reinterpret_cast<float4*>(&H[(size_t)r * 64 + tx * 8]);
        h0[0] = make_float4(v0[0], v0[1], v0[2], v0[3]);
        h0[1] = make_float4(v0[4], v0[5], v0[6], v0[7]);
        float4* h1 = reinterpret_cast<float4*>(&H[(size_t)(r + 1) * 64 + tx * 8]);
        h1[0] = make_float4(v1[0], v1[1], v1[2], v1[3]);
        h1[1] = make_float4(v1[4], v1[5], v1[6], v1[7]);
    }
    __syncthreads();
    // stats: 32 groups x 64 cols: sums [0,2048), sumsq [2048,4096) in As (=4096)
    #pragma unroll
    for (int j = 0; j < 8; j++) {
        As[ty * 64 + tx * 8 + j]          = ps[j];
        As[2048 + ty * 64 + tx * 8 + j]   = ps2[j];
    }
    __syncthreads();
    if (t < 64) {
        float s = 0.f, s2 = 0.f;
        #pragma unroll
        for (int g = 0; g < 32; g++) { s += As[g * 64 + t]; s2 += As[2048 + g * 64 + t]; }
        atomicAdd(&g_sum[t],   (double)s);
        atomicAdd(&g_sumsq[t], (double)s2);
    }
}

// ---------------------------------------------------------------------------
// Stats of recomputed edge features relu(P+Q+b) over all edges
// ---------------------------------------------------------------------------
template <int CH>
__global__ void stats_edges_kernel(const float* __restrict__ PQ,
                                   const int* __restrict__ IDXp,
                                   const float* __restrict__ bias) {
    constexpr int G = 256 / CH;
    int c = threadIdx.x % CH;
    int g = threadIdx.x / CH;
    float bb = bias[c];
    float s = 0.f, s2 = 0.f;
    for (int node = blockIdx.x * G + g; node < NROW; node += 128 * G) {
        float p = PQ[(size_t)node * (2 * CH) + c] + bb;
        int base = (node >> 10) << 10;
        const int* ix = IDXp + node * KNN;
        #pragma unroll 5
        for (int kk = 0; kk < KNN; kk++) {
            int j = base + ix[kk];
            float v = fmaxf(p + PQ[(size_t)j * (2 * CH) + CH + c], 0.f);
            s += v; s2 = fmaf(v, v, s2);
        }
    }
    __shared__ float sh[2][256];
    sh[0][threadIdx.x] = s; sh[1][threadIdx.x] = s2;
    __syncthreads();
    if (g == 0) {
        #pragma unroll
        for (int gg = 1; gg < G; gg++) { s += sh[0][gg * CH + c]; s2 += sh[1][gg * CH + c]; }
        atomicAdd(&g_sum[c],   (double)s);
        atomicAdd(&g_sumsq[c], (double)s2);
    }
}

// ---------------------------------------------------------------------------
template <int CH>
__global__ void finalize_kernel(const float* __restrict__ gam,
                                const float* __restrict__ bet, int E) {
    int c = threadIdx.x;   // 128
    if (c < CH) {
        double mu  = g_sum[c] / (double)E;
        double var = g_sumsq[c] / (double)E - mu * mu;
        float s = gam[c] * rsqrtf((float)var + 1e-5f);
        g_sc[c] = s;
        g_cc[c] = bet[c] - (float)mu * s;
    }
    g_sum[c] = 0.0; g_sumsq[c] = 0.0;
}

__global__ void fold_kernel(const float* __restrict__ gam, const float* __restrict__ bet,
                            const float* __restrict__ W, const float* __restrict__ bias,
                            int E, float* __restrict__ Wf, float* __restrict__ bf) {
    __shared__ float s_s[64], s_c[64];
    int t = threadIdx.x;   // 256
    if (t < 64) {
        double mu  = g_sum[t] / (double)E;
        double var = g_sumsq[t] / (double)E - mu * mu;
        float s = gam[t] * rsqrtf((float)var + 1e-5f);
        s_s[t] = s;
        s_c[t] = bet[t] - (float)mu * s;
        g_sum[t] = 0.0; g_sumsq[t] = 0.0;
    } else if (t < 128) {
        g_sum[t] = 0.0; g_sumsq[t] = 0.0;
    }
    __syncthreads();
    for (int e = t; e < 64 * 64; e += 256) Wf[e] = s_s[e >> 6] * W[e];
    if (t < 64) {
        float acc = bias[t];
        #pragma unroll 4
        for (int kk = 0; kk < 64; kk++) acc = fmaf(s_c[kk], W[kk * 64 + t], acc);
        bf[t] = acc;
    }
}

// ---------------------------------------------------------------------------
__global__ void maxagg1_kernel(const float* __restrict__ H, float* __restrict__ hcat,
                               float* __restrict__ x1, float* __restrict__ sq) {
    int bi = blockIdx.x;
    int c  = threadIdx.x;   // 64
    const float* h = H + (size_t)bi * (KNN * 64) + c;
    float s = g_sc[c], cc = g_cc[c];
    float m = -3.4e38f;
    #pragma unroll
    for (int kk = 0; kk < KNN; kk++) m = fmaxf(m, fmaf(s, h[kk * 64], cc));
    hcat[(size_t)bi * 192 + c] = m;
    x1[(size_t)bi * 64 + c]    = m;
    float q = m * m;
    #pragma unroll
    for (int o = 16; o; o >>= 1) q += __shfl_xor_sync(0xffffffffu, q, o);
    __shared__ float sh[2];
    if ((c & 31) == 0) sh[c >> 5] = q;
    __syncthreads();
    if (c == 0) sq[bi] = sh[0] + sh[1];
}

__global__ void maxagg_edges_kernel(const float* __restrict__ PQ2,
                                    const int* __restrict__ IDXp,
                                    const float* __restrict__ bias,
                                    float* __restrict__ hcat) {
    int bi = blockIdx.x;
    int c  = threadIdx.x;   // 128
    __shared__ int jj[KNN];
    if (c < KNN) jj[c] = IDXp[bi * KNN + c];
    __syncthreads();
    int base = (bi >> 10) << 10;
    float p = PQ2[(size_t)bi * 256 + c] + bias[c];
    float s = g_sc[c], cc = g_cc[c];
    float m = -3.4e38f;
    #pragma unroll 5
    for (int kk = 0; kk < KNN; kk++) {
        float v = fmaxf(p + PQ2[(size_t)(base + jj[kk]) * 256 + 128 + c], 0.f);
        m = fmaxf(m, fmaf(s, v, cc));
    }
    hcat[(size_t)bi * 192 + 64 + c] = m;
}

__global__ void apply_bn_kernel(const float* __restrict__ Y, float* __restrict__ out) {
    int i = blockIdx.x * 256 + threadIdx.x;
    int c = i & 127;
    out[i] = fmaf(g_sc[c], Y[i], g_cc[c]);
}

// ---------------------------------------------------------------------------
extern "C" void kernel_launch(void* const* d_in, const int* in_sizes, int n_in,
                              void* d_out, int out_size) {
    const float* x0    = (const float*)d_in[1];
    const float* c1w0  = (const float*)d_in[2];
    const float* c1b0  = (const float*)d_in[3];
    const float* c1g0  = (const float*)d_in[4];
    const float* c1be0 = (const float*)d_in[5];
    const float* c1w1  = (const float*)d_in[6];
    const float* c1b1  = (const float*)d_in[7];
    const float* c1g1  = (const float*)d_in[8];
    const float* c1be1 = (const float*)d_in[9];
    const float* c1w2  = (const float*)d_in[10];
    const float* c1b2  = (const float*)d_in[11];
    const float* c1g2  = (const float*)d_in[12];
    const float* c1be2 = (const float*)d_in[13];
    const float* c2w0  = (const float*)d_in[14];
    const float* c2b0  = (const float*)d_in[15];
    const float* c2g0  = (const float*)d_in[16];
    const float* c2be0 = (const float*)d_in[17];
    const float* lw    = (const float*)d_in[18];
    const float* lb    = (const float*)d_in[19];
    const float* lg    = (const float*)d_in[20];
    const float* lbe   = (const float*)d_in[21];
    float* out = (float*)d_out;

    void* sp = nullptr; cudaGetSymbolAddress(&sp, g_scratch);
    float* S = (float*)sp;
    void* ip = nullptr; cudaGetSymbolAddress(&ip, g_knn_idx);
    int* IDX = (int*)ip;

    float* D     = S + OFF_D;
    float* PQ    = S + OFF_PQ;
    float* PQ2   = S + OFF_PQ2;
    float* H1    = S + OFF_H1;
    float* H2    = S + OFF_H2;
    float* HCAT  = S + OFF_HCAT;
    float* X1    = S + OFF_X1;
    float* Y0    = S + OFF_Y0;
    float* SQ    = S + OFF_SQ;
    float* WCAT  = S + OFF_WCAT;
    float* WCAT2 = S + OFF_WCAT2;
    float* WF    = S + OFF_WF;
    float* BF    = S + OFF_BF;

    // dependency-free weight prep first => ncu capture slot lands on dist1
    build_wcat1<<<128, 256>>>(c1w0, WCAT);
    build_wcat2<<<64, 256>>>(c2w0, WCAT2);
    rowsq_kernel<256><<<NROW, 32>>>(x0, SQ);

    // ---- EdgeConv 1 ----
    dist_kernel<256><<<dim3(8, 8, 8), 256>>>(x0, SQ, D);
    topk_kernel<<<NROW / 8, 256>>>(D, IDX);
    gemm_nodes<128, 128, false, false><<<dim3(1, NROW / 128), 256>>>(x0, WCAT, nullptr, PQ, NROW, 128, 256);
    stats_edges_kernel<64><<<128, 256>>>(PQ, IDX, c1b0);
    fold_kernel<<<1, 256>>>(c1g0, c1be0, c1w1, c1b1, NEDGE, WF, BF);
    gemm_edge1<<<NEDGE / 256, 256>>>(PQ, IDX, c1b0, WF, BF, H1);
    fold_kernel<<<1, 256>>>(c1g1, c1be1, c1w2, c1b2, NEDGE, WF, BF);
    gemm_nodes<256, 64, true, true><<<dim3(1, NEDGE / 256), 256>>>(H1, WF, BF, H2, NEDGE, 64, 64);
    finalize_kernel<64><<<1, 128>>>(c1g2, c1be2, NEDGE);
    maxagg1_kernel<<<NROW, 64>>>(H2, HCAT, X1, SQ);

    // ---- EdgeConv 2 ----
    dist_kernel<64><<<dim3(8, 8, 8), 256>>>(X1, SQ, D);
    topk_kernel<<<NROW / 8, 256>>>(D, IDX);
    gemm_nodes<128, 128, false, false><<<dim3(2, NROW / 128), 256>>>(X1, WCAT2, nullptr, PQ2, NROW, 256, 64);
    stats_edges_kernel<128><<<128, 256>>>(PQ2, IDX, c2b0);
    finalize_kernel<128><<<1, 128>>>(c2g0, c2be0, NEDGE);
    maxagg_edges_kernel<<<NROW, 128>>>(PQ2, IDX, c2b0, HCAT);

    // ---- Final Linear + BN ----
    gemm_nodes<128, 128, true, true><<<dim3(1, NROW / 128), 256>>>(HCAT, lw, lb, Y0, NROW, 128, 192);
    finalize_kernel<128><<<1, 128>>>(lg, lbe, NROW);
    apply_bn_kernel<<<NROW * 128 / 256, 256>>>(Y0, out);
}

// round 8
// speedup vs baseline: 2.0915x; 2.0915x over previous
#include <cuda_runtime.h>
#include <cstdint>

// ---------------------------------------------------------------------------
// DGCNN: 2x EdgeConv (dynamic kNN) + final MLP, training-mode BatchNorm.
// R8 = proven R2 base (543us) + (a) symmetric dist: only upper-triangle tiles
// computed, mirror tile written transposed (44% FLOP cut on dist), and
// (b) coalesced float4 top-k loads (8x fewer L1 wavefronts).
// ---------------------------------------------------------------------------

typedef unsigned long long ull;

namespace cfg {
constexpr int BB   = 8;
constexpr int NN_  = 1024;
constexpr int KNN  = 20;
constexpr int NROW  = BB * NN_;        // 8192
constexpr int NEDGE = NROW * KNN;      // 163840

constexpr size_t OFF_D    = 0;
constexpr size_t SZ_D     = (size_t)BB * NN_ * NN_;
constexpr size_t OFF_PQ   = OFF_D + SZ_D;
constexpr size_t SZ_PQ    = (size_t)NROW * 128;
constexpr size_t OFF_PQ2  = OFF_PQ + SZ_PQ;
constexpr size_t SZ_PQ2   = (size_t)NROW * 256;
constexpr size_t OFF_H1   = OFF_PQ2 + SZ_PQ2;
constexpr size_t SZ_H64   = (size_t)NEDGE * 64;
constexpr size_t OFF_H2   = OFF_H1 + SZ_H64;
constexpr size_t OFF_HCAT = OFF_H2 + SZ_H64;
constexpr size_t SZ_HCAT  = (size_t)NROW * 192;
constexpr size_t OFF_X1   = OFF_HCAT + SZ_HCAT;
constexpr size_t SZ_X1    = (size_t)NROW * 64;
constexpr size_t OFF_Y0   = OFF_X1 + SZ_X1;
constexpr size_t SZ_Y0    = (size_t)NROW * 128;
constexpr size_t OFF_SQ   = OFF_Y0 + SZ_Y0;
constexpr size_t SZ_SQ    = (size_t)NROW;
constexpr size_t OFF_WCAT = OFF_SQ + SZ_SQ;
constexpr size_t SZ_WCAT  = 256 * 128;
constexpr size_t OFF_WCAT2= OFF_WCAT + SZ_WCAT;
constexpr size_t SZ_WCAT2 = 64 * 256;
constexpr size_t OFF_WF   = OFF_WCAT2 + SZ_WCAT2;
constexpr size_t SZ_WF    = 64 * 64;
constexpr size_t OFF_BF   = OFF_WF + SZ_WF;
constexpr size_t SZ_BF    = 128;
constexpr size_t SCRATCH_TOTAL = OFF_BF + SZ_BF;
}  // namespace cfg
using namespace cfg;

__device__ float  g_scratch[SCRATCH_TOTAL];
__device__ int    g_knn_idx[NEDGE];
__device__ double g_sum[128];
__device__ double g_sumsq[128];
__device__ float  g_sc[128];
__device__ float  g_cc[128];

// ---------------------------------------------------------------------------
__device__ __forceinline__ ull pack2(float x, float y) {
    ull r; asm("mov.b64 %0, {%1, %2};" : "=l"(r) : "f"(x), "f"(y)); return r;
}
__device__ __forceinline__ void fma2(ull& d, ull a, ull b) {
    asm("fma.rn.f32x2 %0, %1, %2, %0;" : "+l"(d) : "l"(a), "l"(b));
}
__device__ __forceinline__ float2 unpack2(ull v) {
    float2 f; asm("mov.b64 {%0, %1}, %2;" : "=f"(f.x), "=f"(f.y) : "l"(v)); return f;
}

// ---------------------------------------------------------------------------
// Combined weights [A-B | B]  (dependency-free; launched first so the ncu
// capture slot lands on dist_kernel)
// ---------------------------------------------------------------------------
__global__ void build_wcat1(const float* __restrict__ W0, float* __restrict__ Wcat) {
    int e = blockIdx.x * 256 + threadIdx.x;    // 256*128
    int kk = e >> 7, n = e & 127;
    float v;
    if (n < 64) v = W0[kk * 64 + n] - W0[(kk + 256) * 64 + n];
    else        v = W0[(kk + 256) * 64 + (n - 64)];
    Wcat[e] = v;
}
__global__ void build_wcat2(const float* __restrict__ W0, float* __restrict__ Wcat) {
    int e = blockIdx.x * 256 + threadIdx.x;    // 64*256
    int kk = e >> 8, n = e & 255;
    float v;
    if (n < 128) v = W0[kk * 128 + n] - W0[(kk + 64) * 128 + n];
    else         v = W0[(kk + 64) * 128 + (n - 128)];
    Wcat[e] = v;
}

// ---------------------------------------------------------------------------
template <int C>
__global__ void rowsq_kernel(const float* __restrict__ X, float* __restrict__ sq) {
    int row = blockIdx.x;
    const float* x = X + (size_t)row * C;
    float a = 0.f;
    #pragma unroll
    for (int c = threadIdx.x; c < C; c += 32) { float v = x[c]; a = fmaf(v, v, a); }
    #pragma unroll
    for (int o = 16; o; o >>= 1) a += __shfl_xor_sync(0xffffffffu, a, o);
    if (threadIdx.x == 0) sq[row] = a;
}

// ---------------------------------------------------------------------------
// Distance matrix (R2 microkernel), symmetric: grid.x = 36 triangular tiles.
// Tile (bi,bj), bi<=bj: compute 128x128, write normal; if bi!=bj also write
// the transposed mirror tile.
// ---------------------------------------------------------------------------
template <int C>
__global__ void __launch_bounds__(256)
dist_kernel(const float* __restrict__ X, const float* __restrict__ sq,
            float* __restrict__ D) {
    __shared__ float As[16][128];
    __shared__ float Bs[16][128];
    int b  = blockIdx.z;
    const float* Xb  = X  + (size_t)b * NN_ * C;
    const float* sqb = sq + (size_t)b * NN_;
    float* Db = D + (size_t)b * NN_ * NN_;

    // triangular decode: blockIdx.x in [0,36) -> (bi, bj), bi <= bj
    int rem = blockIdx.x, bi = 0;
    while (rem >= 8 - bi) { rem -= 8 - bi; bi++; }
    int bj = bi + rem;
    int i0 = bi * 128, j0 = bj * 128;

    int t  = threadIdx.x;
    int tx = t & 15, ty = t >> 4;

    ull acc[8][4];
    #pragma unroll
    for (int i = 0; i < 8; i++)
        #pragma unroll
        for (int j = 0; j < 4; j++) acc[i][j] = 0ull;

    for (int k0 = 0; k0 < C; k0 += 16) {
        #pragma unroll
        for (int it = 0; it < 2; it++) {
            int r  = (t >> 2) + it * 64;
            int kk = (t & 3) * 4;
            float4 va = *reinterpret_cast<const float4*>(&Xb[(size_t)(i0 + r) * C + k0 + kk]);
            As[kk + 0][r] = va.x; As[kk + 1][r] = va.y;
            As[kk + 2][r] = va.z; As[kk + 3][r] = va.w;
            float4 vb = *reinterpret_cast<const float4*>(&Xb[(size_t)(j0 + r) * C + k0 + kk]);
            Bs[kk + 0][r] = vb.x; Bs[kk + 1][r] = vb.y;
            Bs[kk + 2][r] = vb.z; Bs[kk + 3][r] = vb.w;
        }
        __syncthreads();
        #pragma unroll
        for (int kk = 0; kk < 16; kk++) {
            float4 a0 = *reinterpret_cast<const float4*>(&As[kk][ty * 8]);
            float4 a1 = *reinterpret_cast<const float4*>(&As[kk][ty * 8 + 4]);
            float4 b0 = *reinterpret_cast<const float4*>(&Bs[kk][tx * 8]);
            float4 b1 = *reinterpret_cast<const float4*>(&Bs[kk][tx * 8 + 4]);
            ull rb[4] = {pack2(b0.x, b0.y), pack2(b0.z, b0.w),
                         pack2(b1.x, b1.y), pack2(b1.z, b1.w)};
            float ra[8] = {a0.x, a0.y, a0.z, a0.w, a1.x, a1.y, a1.z, a1.w};
            #pragma unroll
            for (int i = 0; i < 8; i++) {
                ull ai = pack2(ra[i], ra[i]);
                #pragma unroll
                for (int j = 0; j < 4; j++) fma2(acc[i][j], ai, rb[j]);
            }
        }
        __syncthreads();
    }
    float sj[8];
    #pragma unroll
    for (int j = 0; j < 8; j++) sj[j] = sqb[j0 + tx * 8 + j];

    float o[8][8];
    #pragma unroll
    for (int i = 0; i < 8; i++) {
        float si = sqb[i0 + ty * 8 + i];
        #pragma unroll
        for (int j = 0; j < 4; j++) {
            float2 u = unpack2(acc[i][j]);
            o[i][j * 2]     = si + sj[j * 2]     - 2.f * u.x;
            o[i][j * 2 + 1] = si + sj[j * 2 + 1] - 2.f * u.y;
        }
    }
    // normal tile write (coalesced)
    #pragma unroll
    for (int i = 0; i < 8; i++) {
        int gi = i0 + ty * 8 + i;
        float4* dst = reinterpret_cast<float4*>(&Db[(size_t)gi * NN_ + j0 + tx * 8]);
        dst[0] = make_float4(o[i][0], o[i][1], o[i][2], o[i][3]);
        dst[1] = make_float4(o[i][4], o[i][5], o[i][6], o[i][7]);
    }
    // mirror tile write (transposed; 2 lanes/row contiguous -> 1 sector/row)
    if (bi != bj) {
        #pragma unroll
        for (int j = 0; j < 8; j++) {
            int gj = j0 + tx * 8 + j;
            float4* dst = reinterpret_cast<float4*>(&Db[(size_t)gj * NN_ + i0 + ty * 8]);
            dst[0] = make_float4(o[0][j], o[1][j], o[2][j], o[3][j]);
            dst[1] = make_float4(o[4][j], o[5][j], o[6][j], o[7][j]);
        }
    }
}

// ---------------------------------------------------------------------------
// Top-20 smallest per row; one warp per row. Coalesced float4 loads:
// lane owns v[4q+r] = d[4*lane + 128*q + r]  (contiguous 512B per warp-LDG).
// ---------------------------------------------------------------------------
__global__ void topk_kernel(const float* __restrict__ D, int* __restrict__ idx) {
    int row  = blockIdx.x * 8 + (threadIdx.x >> 5);
    int lane = threadIdx.x & 31;
    const float4* d4 = reinterpret_cast<const float4*>(D + (size_t)row * NN_);
    float v[32];
    #pragma unroll
    for (int q = 0; q < 8; q++) {
        float4 x = d4[lane + 32 * q];
        v[4 * q + 0] = x.x; v[4 * q + 1] = x.y;
        v[4 * q + 2] = x.z; v[4 * q + 3] = x.w;
    }

    for (int s = 0; s < KNN; s++) {
        float m = v[0]; int mq = 0;
        #pragma unroll
        for (int q = 1; q < 32; q++) { if (v[q] < m) { m = v[q]; mq = q; } }
        // global index of local slot mq = 4q+r  ->  4*lane + 128*q + r
        int gidx = 4 * lane + 128 * (mq >> 2) + (mq & 3);
        float bm = m; int bidx = gidx;
        #pragma unroll
        for (int o = 16; o; o >>= 1) {
            float om = __shfl_xor_sync(0xffffffffu, bm, o);
            int   oi = __shfl_xor_sync(0xffffffffu, bidx, o);
            if (om < bm || (om == bm && oi < bidx)) { bm = om; bidx = oi; }
        }
        if (lane == 0) idx[row * KNN + s] = bidx;
        // winner lane zeroes its slot: lane = (bidx>>2)&31, slot = 4*(bidx>>7)+(bidx&3)
        int wl = (bidx >> 2) & 31;
        if (lane == wl) {
            int slot = 4 * (bidx >> 7) + (bidx & 3);
            #pragma unroll
            for (int q = 0; q < 32; q++) if (q == slot) v[q] = 3.4e38f;
        }
    }
}

// ---------------------------------------------------------------------------
// Generic fp32 GEMM (f32x2): C = A[M,K] @ B[K,N] (+bias,relu) (+col stats)
// 256 threads; TX = BN/TN must be 16, 256/TX rows of TM each -> BM.
// ---------------------------------------------------------------------------
template <int BM, int BN, int TM, int TN, bool BIAS_RELU, bool STATS>
__global__ void __launch_bounds__(256)
gemm_nodes(const float* __restrict__ A, const float* __restrict__ Bm,
           const float* __restrict__ bias, float* __restrict__ Cmat,
           int M, int N, int K) {
    constexpr int BK = 16;
    constexpr int TX = BN / TN;
    static_assert(TX == 16 && (256 / TX) * TM == BM, "layout");
    __shared__ float smem[BK * (BM + BN)];
    float* As = smem;
    float* Bs = smem + BK * BM;
    int block_m = blockIdx.y * BM, block_n = blockIdx.x * BN;
    int t  = threadIdx.x;
    int tx = t % TX, ty = t / TX;

    ull acc[TM][TN / 2];
    #pragma unroll
    for (int i = 0; i < TM; i++)
        #pragma unroll
        for (int j = 0; j < TN / 2; j++) acc[i][j] = 0ull;

    for (int k0 = 0; k0 < K; k0 += BK) {
        #pragma unroll
        for (int it = 0; it < BM / 64; it++) {
            int r  = (t >> 2) + it * 64;
            int kk = (t & 3) * 4;
            float4 v = *reinterpret_cast<const float4*>(&A[(size_t)(block_m + r) * K + k0 + kk]);
            As[(kk + 0) * BM + r] = v.x; As[(kk + 1) * BM + r] = v.y;
            As[(kk + 2) * BM + r] = v.z; As[(kk + 3) * BM + r] = v.w;
        }
        #pragma unroll
        for (int it = 0; it < BN / 64; it++) {
            int kk = t >> 4;
            int cc = (t & 15) * 4 + it * 64;
            *reinterpret_cast<float4*>(&Bs[kk * BN + cc]) =
                *reinterpret_cast<const float4*>(&Bm[(size_t)(k0 + kk) * N + block_n + cc]);
        }
        __syncthreads();
        #pragma unroll
        for (int kk = 0; kk < BK; kk++) {
            float ra[TM];
            #pragma unroll
            for (int i4 = 0; i4 < TM / 4; i4++) {
                float4 a = *reinterpret_cast<const float4*>(&As[kk * BM + ty * TM + i4 * 4]);
                ra[i4 * 4 + 0] = a.x; ra[i4 * 4 + 1] = a.y;
                ra[i4 * 4 + 2] = a.z; ra[i4 * 4 + 3] = a.w;
            }
            ull rb[TN / 2];
            #pragma unroll
            for (int j4 = 0; j4 < TN / 4; j4++) {
                float4 bq = *reinterpret_cast<const float4*>(&Bs[kk * BN + tx * TN + j4 * 4]);
                rb[j4 * 2 + 0] = pack2(bq.x, bq.y);
                rb[j4 * 2 + 1] = pack2(bq.z, bq.w);
            }
            #pragma unroll
            for (int i = 0; i < TM; i++) {
                ull ai = pack2(ra[i], ra[i]);
                #pragma unroll
                for (int j = 0; j < TN / 2; j++) fma2(acc[i][j], ai, rb[j]);
            }
        }
        __syncthreads();
    }

    float bb[TN];
    if (BIAS_RELU) {
        #pragma unroll
        for (int j = 0; j < TN; j++) bb[j] = bias[block_n + tx * TN + j];
    }
    float ps[TN], ps2[TN];
    #pragma unroll
    for (int j = 0; j < TN; j++) { ps[j] = 0.f; ps2[j] = 0.f; }

    #pragma unroll
    for (int i = 0; i < TM; i++) {
        float v[TN];
        #pragma unroll
        for (int j = 0; j < TN / 2; j++) {
            float2 u = unpack2(acc[i][j]);
            v[j * 2] = u.x; v[j * 2 + 1] = u.y;
        }
        #pragma unroll
        for (int j = 0; j < TN; j++) {
            if (BIAS_RELU) v[j] = fmaxf(v[j] + bb[j], 0.f);
            if (STATS) { ps[j] += v[j]; ps2[j] = fmaf(v[j], v[j], ps2[j]); }
        }
        int r = block_m + ty * TM + i;
        #pragma unroll
        for (int j4 = 0; j4 < TN / 4; j4++)
            *reinterpret_cast<float4*>(&Cmat[(size_t)r * N + block_n + tx * TN + j4 * 4]) =
                make_float4(v[j4 * 4], v[j4 * 4 + 1], v[j4 * 4 + 2], v[j4 * 4 + 3]);
    }

    if (STATS) {
        // reuse smem: [0, 16*BN) sums, [16*BN, 32*BN) sumsq (fits: BM >= BN)
        #pragma unroll
        for (int j = 0; j < TN; j++) {
            smem[ty * BN + tx * TN + j]           = ps[j];
            smem[16 * BN + ty * BN + tx * TN + j] = ps2[j];
        }
        __syncthreads();
        if (t < BN) {
            float s = 0.f, s2 = 0.f;
            #pragma unroll
            for (int g = 0; g < 16; g++) { s += smem[g * BN + t]; s2 += smem[16 * BN + g * BN + t]; }
            atomicAdd(&g_sum[t],   (double)s);
            atomicAdd(&g_sumsq[t], (double)s2);
        }
    }
}

// ---------------------------------------------------------------------------
// Layer-1 edge GEMM: A recomputed on the fly: A[e,c]=relu(P[i,c]+Q[j,c]+b[c]),
// B = folded W1 [64,64], out H1 + fused col stats. M=NEDGE, N=K=64.
// ---------------------------------------------------------------------------
__global__ void __launch_bounds__(256)
gemm_edge1(const float* __restrict__ PQ, const int* __restrict__ IDXp,
           const float* __restrict__ abias, const float* __restrict__ W,
           const float* __restrict__ obias, float* __restrict__ H) {
    __shared__ float As[16 * 128];
    __shared__ float Bs[16 * 64];
    __shared__ int   s_bi[128], s_qo[128];
    __shared__ float s_ab[64];
    int t = threadIdx.x;
    int block_m = blockIdx.x * 128;
    if (t < 128) {
        int e = block_m + t;
        int bi = e / KNN;
        s_bi[t] = bi;
        s_qo[t] = ((bi >> 10) << 10) + IDXp[e];
    }
    if (t < 64) s_ab[t] = abias[t];
    __syncthreads();

    int tx = t & 15, ty = t >> 4;
    ull acc[8][2];
    #pragma unroll
    for (int i = 0; i < 8; i++) { acc[i][0] = 0ull; acc[i][1] = 0ull; }

    for (int k0 = 0; k0 < 64; k0 += 16) {
        {   // A tile: 128 rows x 16 cols; thread -> row t>>1, 8 cols
            int r  = t >> 1;
            int co = (t & 1) * 8;
            int bi = s_bi[r], qo = s_qo[r];
            const float* Pp = PQ + (size_t)bi * 128 + k0 + co;
            const float* Qp = PQ + (size_t)qo * 128 + 64 + k0 + co;
            float4 p0 = *reinterpret_cast<const float4*>(Pp);
            float4 p1 = *reinterpret_cast<const float4*>(Pp + 4);
            float4 q0 = *reinterpret_cast<const float4*>(Qp);
            float4 q1 = *reinterpret_cast<const float4*>(Qp + 4);
            As[(co + 0) * 128 + r] = fmaxf(p0.x + q0.x + s_ab[k0 + co + 0], 0.f);
            As[(co + 1) * 128 + r] = fmaxf(p0.y + q0.y + s_ab[k0 + co + 1], 0.f);
            As[(co + 2) * 128 + r] = fmaxf(p0.z + q0.z + s_ab[k0 + co + 2], 0.f);
            As[(co + 3) * 128 + r] = fmaxf(p0.w + q0.w + s_ab[k0 + co + 3], 0.f);
            As[(co + 4) * 128 + r] = fmaxf(p1.x + q1.x + s_ab[k0 + co + 4], 0.f);
            As[(co + 5) * 128 + r] = fmaxf(p1.y + q1.y + s_ab[k0 + co + 5], 0.f);
            As[(co + 6) * 128 + r] = fmaxf(p1.z + q1.z + s_ab[k0 + co + 6], 0.f);
            As[(co + 7) * 128 + r] = fmaxf(p1.w + q1.w + s_ab[k0 + co + 7], 0.f);
        }
        {   // B tile 16x64: two 8-row K-slabs, both at k0+kk and k0+kk+8
            int kk = t >> 4, cc = (t & 15) * 4;
            *reinterpret_cast<float4*>(&Bs[kk * 64 + cc]) =
                *reinterpret_cast<const float4*>(&W[(size_t)(k0 + kk) * 64 + cc]);
        }
        __syncthreads();
        #pragma unroll
        for (int kk = 0; kk < 16; kk++) {
            float4 a0 = *reinterpret_cast<const float4*>(&As[kk * 128 + ty * 8]);
            float4 a1 = *reinterpret_cast<const float4*>(&As[kk * 128 + ty * 8 + 4]);
            float4 b0 = *reinterpret_cast<const float4*>(&Bs[kk * 64 + tx * 4]);
            ull rb0 = pack2(b0.x, b0.y), rb1 = pack2(b0.z, b0.w);
            float ra[8] = {a0.x, a0.y, a0.z, a0.w, a1.x, a1.y, a1.z, a1.w};
            #pragma unroll
            for (int i = 0; i < 8; i++) {
                ull ai = pack2(ra[i], ra[i]);
                fma2(acc[i][0], ai, rb0);
                fma2(acc[i][1], ai, rb1);
            }
        }
        __syncthreads();
    }
    float ob[4];
    #pragma unroll
    for (int j = 0; j < 4; j++) ob[j] = obias[tx * 4 + j];
    float ps[4] = {0, 0, 0, 0}, ps2[4] = {0, 0, 0, 0};
    #pragma unroll
    for (int i = 0; i < 8; i++) {
        float2 u0 = unpack2(acc[i][0]), u1 = unpack2(acc[i][1]);
        float v[4] = {u0.x, u0.y, u1.x, u1.y};
        #pragma unroll
        for (int j = 0; j < 4; j++) {
            v[j] = fmaxf(v[j] + ob[j], 0.f);
            ps[j] += v[j]; ps2[j] = fmaf(v[j], v[j], ps2[j]);
        }
        int r = block_m + ty * 8 + i;
        *reinterpret_cast<float4*>(&H[(size_t)r * 64 + tx * 4]) =
            make_float4(v[0], v[1], v[2], v[3]);
    }
    // stats reduce (reuse As: 16*64 sums + 16*64 sumsq = 2048 floats)
    #pragma unroll
    for (int j = 0; j < 4; j++) {
        As[ty * 64 + tx * 4 + j]        = ps[j];
        As[1024 + ty * 64 + tx * 4 + j] = ps2[j];
    }
    __syncthreads();
    if (t < 64) {
        float s = 0.f, s2 = 0.f;
        #pragma unroll
        for (int g = 0; g < 16; g++) { s += As[g * 64 + t]; s2 += As[1024 + g * 64 + t]; }
        atomicAdd(&g_sum[t],   (double)s);
        atomicAdd(&g_sumsq[t], (double)s2);
    }
}

// ---------------------------------------------------------------------------
// Stats of recomputed edge features relu(P+Q+b) over all edges
// ---------------------------------------------------------------------------
template <int CH>
__global__ void stats_edges_kernel(const float* __restrict__ PQ,
                                   const int* __restrict__ IDXp,
                                   const float* __restrict__ bias) {
    constexpr int G = 256 / CH;
    int c = threadIdx.x % CH;
    int g = threadIdx.x / CH;
    float bb = bias[c];
    float s = 0.f, s2 = 0.f;
    for (int node = blockIdx.x * G + g; node < NROW; node += 128 * G) {
        float p = PQ[(size_t)node * (2 * CH) + c] + bb;
        int base = (node >> 10) << 10;
        const int* ix = IDXp + node * KNN;
        #pragma unroll 5
        for (int kk = 0; kk < KNN; kk++) {
            int j = base + ix[kk];
            float v = fmaxf(p + PQ[(size_t)j * (2 * CH) + CH + c], 0.f);
            s += v; s2 = fmaf(v, v, s2);
        }
    }
    __shared__ float sh[2][256];
    sh[0][threadIdx.x] = s; sh[1][threadIdx.x] = s2;
    __syncthreads();
    if (g == 0) {
        #pragma unroll
        for (int gg = 1; gg < G; gg++) { s += sh[0][gg * CH + c]; s2 += sh[1][gg * CH + c]; }
        atomicAdd(&g_sum[c],   (double)s);
        atomicAdd(&g_sumsq[c], (double)s2);
    }
}

// ---------------------------------------------------------------------------
template <int CH>
__global__ void finalize_kernel(const float* __restrict__ gam,
                                const float* __restrict__ bet, int E) {
    int c = threadIdx.x;   // 128
    if (c < CH) {
        double mu  = g_sum[c] / (double)E;
        double var = g_sumsq[c] / (double)E - mu * mu;
        float s = gam[c] * rsqrtf((float)var + 1e-5f);
        g_sc[c] = s;
        g_cc[c] = bet[c] - (float)mu * s;
    }
    g_sum[c] = 0.0; g_sumsq[c] = 0.0;
}

__global__ void fold_kernel(const float* __restrict__ gam, const float* __restrict__ bet,
                            const float* __restrict__ W, const float* __restrict__ bias,
                            int E, float* __restrict__ Wf, float* __restrict__ bf) {
    __shared__ float s_s[64], s_c[64];
    int t = threadIdx.x;   // 256
    if (t < 64) {
        double mu  = g_sum[t] / (double)E;
        double var = g_sumsq[t] / (double)E - mu * mu;
        float s = gam[t] * rsqrtf((float)var + 1e-5f);
        s_s[t] = s;
        s_c[t] = bet[t] - (float)mu * s;
        g_sum[t] = 0.0; g_sumsq[t] = 0.0;
    } else if (t < 128) {
        g_sum[t] = 0.0; g_sumsq[t] = 0.0;
    }
    __syncthreads();
    for (int e = t; e < 64 * 64; e += 256) Wf[e] = s_s[e >> 6] * W[e];
    if (t < 64) {
        float acc = bias[t];
        #pragma unroll 4
        for (int kk = 0; kk < 64; kk++) acc = fmaf(s_c[kk], W[kk * 64 + t], acc);
        bf[t] = acc;
    }
}

// ---------------------------------------------------------------------------
__global__ void maxagg1_kernel(const float* __restrict__ H, float* __restrict__ hcat,
                               float* __restrict__ x1, float* __restrict__ sq) {
    int bi = blockIdx.x;
    int c  = threadIdx.x;   // 64
    const float* h = H + (size_t)bi * (KNN * 64) + c;
    float s = g_sc[c], cc = g_cc[c];
    float m = -3.4e38f;
    #pragma unroll
    for (int kk = 0; kk < KNN; kk++) m = fmaxf(m, fmaf(s, h[kk * 64], cc));
    hcat[(size_t)bi * 192 + c] = m;
    x1[(size_t)bi * 64 + c]    = m;
    float q = m * m;
    #pragma unroll
    for (int o = 16; o; o >>= 1) q += __shfl_xor_sync(0xffffffffu, q, o);
    __shared__ float sh[2];
    if ((c & 31) == 0) sh[c >> 5] = q;
    __syncthreads();
    if (c == 0) sq[bi] = sh[0] + sh[1];
}

__global__ void maxagg_edges_kernel(const float* __restrict__ PQ2,
                                    const int* __restrict__ IDXp,
                                    const float* __restrict__ bias,
                                    float* __restrict__ hcat) {
    int bi = blockIdx.x;
    int c  = threadIdx.x;   // 128
    __shared__ int jj[KNN];
    if (c < KNN) jj[c] = IDXp[bi * KNN + c];
    __syncthreads();
    int base = (bi >> 10) << 10;
    float p = PQ2[(size_t)bi * 256 + c] + bias[c];
    float s = g_sc[c], cc = g_cc[c];
    float m = -3.4e38f;
    #pragma unroll 5
    for (int kk = 0; kk < KNN; kk++) {
        float v = fmaxf(p + PQ2[(size_t)(base + jj[kk]) * 256 + 128 + c], 0.f);
        m = fmaxf(m, fmaf(s, v, cc));
    }
    hcat[(size_t)bi * 192 + 64 + c] = m;
}

__global__ void apply_bn_kernel(const float* __restrict__ Y, float* __restrict__ out) {
    int i = blockIdx.x * 256 + threadIdx.x;
    int c = i & 127;
    out[i] = fmaf(g_sc[c], Y[i], g_cc[c]);
}

// ---------------------------------------------------------------------------
extern "C" void kernel_launch(void* const* d_in, const int* in_sizes, int n_in,
                              void* d_out, int out_size) {
    const float* x0    = (const float*)d_in[1];
    const float* c1w0  = (const float*)d_in[2];
    const float* c1b0  = (const float*)d_in[3];
    const float* c1g0  = (const float*)d_in[4];
    const float* c1be0 = (const float*)d_in[5];
    const float* c1w1  = (const float*)d_in[6];
    const float* c1b1  = (const float*)d_in[7];
    const float* c1g1  = (const float*)d_in[8];
    const float* c1be1 = (const float*)d_in[9];
    const float* c1w2  = (const float*)d_in[10];
    const float* c1b2  = (const float*)d_in[11];
    const float* c1g2  = (const float*)d_in[12];
    const float* c1be2 = (const float*)d_in[13];
    const float* c2w0  = (const float*)d_in[14];
    const float* c2b0  = (const float*)d_in[15];
    const float* c2g0  = (const float*)d_in[16];
    const float* c2be0 = (const float*)d_in[17];
    const float* lw    = (const float*)d_in[18];
    const float* lb    = (const float*)d_in[19];
    const float* lg    = (const float*)d_in[20];
    const float* lbe   = (const float*)d_in[21];
    float* out = (float*)d_out;

    void* sp = nullptr; cudaGetSymbolAddress(&sp, g_scratch);
    float* S = (float*)sp;
    void* ip = nullptr; cudaGetSymbolAddress(&ip, g_knn_idx);
    int* IDX = (int*)ip;

    float* D     = S + OFF_D;
    float* PQ    = S + OFF_PQ;
    float* PQ2   = S + OFF_PQ2;
    float* H1    = S + OFF_H1;
    float* H2    = S + OFF_H2;
    float* HCAT  = S + OFF_HCAT;
    float* X1    = S + OFF_X1;
    float* Y0    = S + OFF_Y0;
    float* SQ    = S + OFF_SQ;
    float* WCAT  = S + OFF_WCAT;
    float* WCAT2 = S + OFF_WCAT2;
    float* WF    = S + OFF_WF;
    float* BF    = S + OFF_BF;

    // dependency-free weight prep first => ncu capture slot lands on dist1
    build_wcat1<<<128, 256>>>(c1w0, WCAT);
    build_wcat2<<<64, 256>>>(c2w0, WCAT2);
    rowsq_kernel<256><<<NROW, 32>>>(x0, SQ);

    // ---- EdgeConv 1 ----
    dist_kernel<256><<<dim3(36, 1, 8), 256>>>(x0, SQ, D);
    topk_kernel<<<NROW / 8, 256>>>(D, IDX);
    gemm_nodes<128, 128, 8, 8, false, false><<<dim3(1, NROW / 128), 256>>>(x0, WCAT, nullptr, PQ, NROW, 128, 256);
    stats_edges_kernel<64><<<128, 256>>>(PQ, IDX, c1b0);
    fold_kernel<<<1, 256>>>(c1g0, c1be0, c1w1, c1b1, NEDGE, WF, BF);
    gemm_edge1<<<NEDGE / 128, 256>>>(PQ, IDX, c1b0, WF, BF, H1);
    fold_kernel<<<1, 256>>>(c1g1, c1be1, c1w2, c1b2, NEDGE, WF, BF);
    gemm_nodes<128, 64, 8, 4, true, true><<<dim3(1, NEDGE / 128), 256>>>(H1, WF, BF, H2, NEDGE, 64, 64);
    finalize_kernel<64><<<1, 128>>>(c1g2, c1be2, NEDGE);
    maxagg1_kernel<<<NROW, 64>>>(H2, HCAT, X1, SQ);

    // ---- EdgeConv 2 ----
    dist_kernel<64><<<dim3(36, 1, 8), 256>>>(X1, SQ, D);
    topk_kernel<<<NROW / 8, 256>>>(D, IDX);
    gemm_nodes<128, 128, 8, 8, false, false><<<dim3(2, NROW / 128), 256>>>(X1, WCAT2, nullptr, PQ2, NROW, 256, 64);
    stats_edges_kernel<128><<<128, 256>>>(PQ2, IDX, c2b0);
    finalize_kernel<128><<<1, 128>>>(c2g0, c2be0, NEDGE);
    maxagg_edges_kernel<<<NROW, 128>>>(PQ2, IDX, c2b0, HCAT);

    // ---- Final Linear + BN ----
    gemm_nodes<128, 128, 8, 8, true, true><<<dim3(1, NROW / 128), 256>>>(HCAT, lw, lb, Y0, NROW, 128, 192);
    finalize_kernel<128><<<1, 128>>>(lg, lbe, NROW);
    apply_bn_kernel<<<NROW * 128 / 256, 256>>>(Y0, out);
}